// round 6
// baseline (speedup 1.0000x reference)
#include <cuda_runtime.h>
#include <cstdint>

// Problem constants
#define INSZ   128
#define OUTSZ  128
#define BATCH  1024

#define NCHUNK 8
#define BC     (BATCH / NCHUNK)   // 128 batch elems per block
#define TILE   16                 // x staging tile (batch elems)
#define NTILE  (BC / TILE)        // 8
#define PAD    133                // smem row pitch for weight staging

typedef unsigned long long u64;

__device__ __forceinline__ u64 pk(float a, float b) {
    u64 r; asm("mov.b64 %0, {%1, %2};" : "=l"(r) : "f"(a), "f"(b)); return r;
}
__device__ __forceinline__ void upk(u64 v, float& a, float& b) {
    asm("mov.b64 {%0, %1}, %2;" : "=f"(a), "=f"(b) : "l"(v));
}
__device__ __forceinline__ u64 ffma2(u64 a, u64 b, u64 c) {
    u64 d; asm("fma.rn.f32x2 %0, %1, %2, %3;" : "=l"(d) : "l"(a), "l"(b), "l"(c)); return d;
}
__device__ __forceinline__ u64 fmul2(u64 a, u64 b) {
    u64 d; asm("mul.rn.f32x2 %0, %1, %2;" : "=l"(d) : "l"(a), "l"(b)); return d;
}
__device__ __forceinline__ u64 fadd2(u64 a, u64 b) {
    u64 d; asm("add.rn.f32x2 %0, %1, %2;" : "=l"(d) : "l"(a), "l"(b)); return d;
}
__device__ __forceinline__ uint32_t s2u(const void* p) {
    uint32_t a;
    asm("{ .reg .u64 t; cvta.to.shared.u64 t, %1; cvt.u32.u64 %0, t; }" : "=r"(a) : "l"(p));
    return a;
}
__device__ __forceinline__ void cpa16(uint32_t dst, const void* src) {
    asm volatile("cp.async.ca.shared.global [%0], [%1], 16;" :: "r"(dst), "l"(src));
}
#define CP_COMMIT() asm volatile("cp.async.commit_group;" ::: "memory")
#define CP_WAIT1()  asm volatile("cp.async.wait_group 1;" ::: "memory")

// ---------------------------------------------------------------------------
// Fused kernel: block = (o, batch-chunk of 128); thread = input feature i.
// 4 CTAs/SM. Weights staged block-locally into registers (f32x2-packed over
// hidden dim). x streamed via cp.async double-buffered smem tiles (16 elems).
// ---------------------------------------------------------------------------
__global__ void __launch_bounds__(128, 4)
mlpkan_fused(const float* __restrict__ x,
             const float* __restrict__ W1, const float* __restrict__ b1,
             const float* __restrict__ W2, const float* __restrict__ b2,
             const float* __restrict__ W3, const float* __restrict__ b3,
             float* __restrict__ out) {
    const int o     = blockIdx.x;
    const int chunk = blockIdx.y;
    const int i     = threadIdx.x;

    __shared__ float stag[49 * PAD];                   // 26.1 KB; dead after packing
    __shared__ __align__(16) float xs[2][TILE][INSZ];  // 16 KB x double buffer
    float* red = stag;                                 // [16][129] alias (8.3 KB)
    float* pr  = stag + 16 * 129;                      // [8][17]

    const uint32_t xsb = s2u(xs);
    const float* xbase = x + (size_t)chunk * BC * INSZ;

    // ---- prefill x tiles 0 and 1 (fire-and-forget; overlaps weight staging) --
#pragma unroll
    for (int c = 0; c < 4; c++) {
        int flat = c * 128 + i;                        // 16B chunk id (512/tile)
        cpa16(xsb + flat * 16, (const char*)xbase + flat * 16);
    }
    CP_COMMIT();
#pragma unroll
    for (int c = 0; c < 4; c++) {
        int flat = c * 128 + i;
        cpa16(xsb + TILE * INSZ * 4 + flat * 16,
              (const char*)(xbase + TILE * INSZ) + flat * 16);
    }
    CP_COMMIT();

    // =========== Phase A staging: W1 (f0-7), b1 (f8-15), W2 e<32 (f16-47) ====
#pragma unroll
    for (int r = 0; r < 8; r++) {
        int idx = r * 128 + i, ii = idx >> 3, h = idx & 7;
        stag[h * PAD + ii] = W1[(size_t)(ii * OUTSZ + o) * 8 + h];
    }
#pragma unroll
    for (int r = 0; r < 8; r++) {
        int idx = r * 128 + i, ii = idx >> 3, h = idx & 7;
        stag[(8 + h) * PAD + ii] = b1[(size_t)(ii * OUTSZ + o) * 8 + h];
    }
#pragma unroll
    for (int r = 0; r < 32; r++) {
        int idx = r * 128 + i, ii = idx >> 5, e = idx & 31;
        stag[(16 + e) * PAD + ii] = W2[(size_t)(ii * OUTSZ + o) * 64 + e];
    }
    __syncthreads();

    u64 w1p[4], b1p[4], w2p[4][8];
#pragma unroll
    for (int p = 0; p < 4; p++) {
        w1p[p] = pk(stag[(2 * p) * PAD + i], stag[(2 * p + 1) * PAD + i]);
        b1p[p] = pk(stag[(8 + 2 * p) * PAD + i], stag[(9 + 2 * p) * PAD + i]);
    }
#pragma unroll
    for (int p = 0; p < 2; p++)
#pragma unroll
        for (int k = 0; k < 8; k++)
            w2p[p][k] = pk(stag[(16 + (2 * p) * 8 + k) * PAD + i],
                           stag[(16 + (2 * p + 1) * 8 + k) * PAD + i]);
    __syncthreads();

    // ===== Phase B staging: W2 e>=32 (r0-31), b2 (r32-39), W3 (r40-47), b3 (r48)
#pragma unroll
    for (int r = 0; r < 32; r++) {
        int idx = r * 128 + i, ii = idx >> 5, e = idx & 31;
        stag[e * PAD + ii] = W2[(size_t)(ii * OUTSZ + o) * 64 + 32 + e];
    }
#pragma unroll
    for (int r = 0; r < 8; r++) {
        int idx = r * 128 + i, ii = idx >> 3, h = idx & 7;
        stag[(32 + h) * PAD + ii] = b2[(size_t)(ii * OUTSZ + o) * 8 + h];
    }
#pragma unroll
    for (int r = 0; r < 8; r++) {
        int idx = r * 128 + i, ii = idx >> 3, h = idx & 7;
        stag[(40 + h) * PAD + ii] = W3[(size_t)(ii * OUTSZ + o) * 8 + h];
    }
    stag[48 * PAD + i] = b3[(size_t)i * OUTSZ + o];
    __syncthreads();

    u64 b2p[4], w3p[4], b3p;
#pragma unroll
    for (int p = 0; p < 2; p++)
#pragma unroll
        for (int k = 0; k < 8; k++)
            w2p[2 + p][k] = pk(stag[((2 * p) * 8 + k) * PAD + i],
                               stag[((2 * p + 1) * 8 + k) * PAD + i]);
#pragma unroll
    for (int p = 0; p < 4; p++) {
        b2p[p] = pk(stag[(32 + 2 * p) * PAD + i], stag[(33 + 2 * p) * PAD + i]);
        w3p[p] = pk(stag[(40 + 2 * p) * PAD + i], stag[(41 + 2 * p) * PAD + i]);
    }
    b3p = pk(stag[48 * PAD + i], 0.0f);   // bias folds into low half of chain 0
    __syncthreads();                      // stag now reusable as red/pr

    // ======================= main loop over 8 x-tiles ========================
#pragma unroll 1
    for (int t = 0; t < NTILE; t++) {
        CP_WAIT1();            // tile t landed
        __syncthreads();       // visibility of cp.async + red free

        const float* vcol = &xs[t & 1][0][i];
#pragma unroll
        for (int bb = 0; bb < TILE; bb++) {
            float v = vcol[bb * INSZ];     // LDS, conflict-free
            u64 vp = pk(v, v);

            // layer 1: h1 = relu(w1*v + b1) -> splatted pairs s[k]
            u64 s[8];
#pragma unroll
            for (int p = 0; p < 4; p++) {
                u64 tt = ffma2(w1p[p], vp, b1p[p]);
                float ta, tb; upk(tt, ta, tb);
                ta = fmaxf(ta, 0.0f);
                tb = fmaxf(tb, 0.0f);
                s[2 * p]     = pk(ta, ta);
                s[2 * p + 1] = pk(tb, tb);
            }

            // layer 2: 4 packed output-pairs, 8-deep chains (4-way ILP)
            u64 h[4];
#pragma unroll
            for (int q = 0; q < 4; q++) {
                u64 acc = ffma2(w2p[q][0], s[0], b2p[q]);
#pragma unroll
                for (int k = 1; k < 8; k++) acc = ffma2(w2p[q][k], s[k], acc);
                float ha, hb; upk(acc, ha, hb);
                h[q] = pk(fmaxf(ha, 0.0f), fmaxf(hb, 0.0f));
            }

            // layer 3: two 2-deep chains + packed combine
            u64 a0 = ffma2(w3p[0], h[0], b3p);
            u64 a1 = fmul2(w3p[1], h[1]);
            a0 = ffma2(w3p[2], h[2], a0);
            a1 = ffma2(w3p[3], h[3], a1);
            u64 tt = fadd2(a0, a1);
            float x0, x1; upk(tt, x0, x1);

            red[bb * 129 + i] = x0 + x1;
        }
        __syncthreads();       // red complete; all reads of xs[t&1] done

        // prefetch tile t+2 into the buffer just consumed
        if (t + 2 < NTILE) {
            const char* gsrc = (const char*)(xbase + (size_t)(t + 2) * TILE * INSZ);
            uint32_t dst = xsb + (uint32_t)(t & 1) * (TILE * INSZ * 4);
#pragma unroll
            for (int c = 0; c < 4; c++) {
                int flat = c * 128 + i;
                cpa16(dst + flat * 16, gsrc + flat * 16);
            }
        }
        CP_COMMIT();           // unconditional: keeps wait_group bookkeeping simple

        // stage-1 reduction: thread (rb = i&15, rq = i>>4) sums 16 i-values
        {
            const int rb = i & 15, rq = i >> 4;
            const float* rr = &red[rb * 129 + rq * 16];
            float s0 = 0.f, s1 = 0.f, s2 = 0.f, s3 = 0.f;
#pragma unroll
            for (int c = 0; c < 16; c += 4) {
                s0 += rr[c + 0]; s1 += rr[c + 1];
                s2 += rr[c + 2]; s3 += rr[c + 3];
            }
            pr[rq * 17 + rb] = (s0 + s1) + (s2 + s3);
        }
        __syncthreads();

        // stage-2: 16 lanes of warp 0 combine 8 partials each + store
        if (i < 16) {
            float r = 0.f;
#pragma unroll
            for (int q = 0; q < 8; q++) r += pr[q * 17 + i];
            out[(size_t)(chunk * BC + t * TILE + i) * OUTSZ + o] = r;
        }
    }
}

// ---------------------------------------------------------------------------
extern "C" void kernel_launch(void* const* d_in, const int* in_sizes, int n_in,
                              void* d_out, int out_size) {
    const float* x  = (const float*)d_in[0];
    const float* W1 = (const float*)d_in[1];
    const float* b1 = (const float*)d_in[2];
    const float* W2 = (const float*)d_in[3];
    const float* b2 = (const float*)d_in[4];
    const float* W3 = (const float*)d_in[5];
    const float* b3 = (const float*)d_in[6];
    float* out = (float*)d_out;

    mlpkan_fused<<<dim3(OUTSZ, NCHUNK), INSZ>>>(x, W1, b1, W2, b2, W3, b3, out);
}